// round 4
// baseline (speedup 1.0000x reference)
#include <cuda_runtime.h>
#include <cuda_bf16.h>
#include <cstdint>

// Problem constants
#define T_ 64
#define B_ 16
#define DIM_ 512
#define H_ 8
#define DH_ 64
#define ETA_ 4
#define FD_ 256           // ETA_*DH_
#define NPROJ 2656        // 5*512 + 3*32
#define NPROJ_PAD 2688    // 21 * 128
#define MROWS 1024        // T_*B_

// Output layout (tuple flattened): output[T,B,DIM], kv_last[B,H,FD,Dh], nm_last[B,H,FD]
#define OUT_OFF_KV  (T_*B_*DIM_)                 // 524288
#define OUT_OFF_NM  (OUT_OFF_KV + B_*H_*FD_*DH_) // 524288 + 2097152

// Scratch (device globals — no allocation allowed)
__device__ float g_proj[MROWS * NPROJ_PAD];        // ~11 MB, projections row-major
__device__ float g_attn[MROWS * (H_*DH_)];         // 2 MB, attn_out before Wo
__device__ float g_outp[4 * MROWS * DIM_];         // 8 MB, split-K partials

// ---------------------------------------------------------------------------
// GEMM 1: projections.  C[m, n] = sum_k X[m,k] * W(n)[k]
// 128x128 tile, BK=8, 256 threads, 8x8 microtile, double-buffered smem.
// ---------------------------------------------------------------------------
#define PBM 128
#define PBN 128
#define PBK 8

__global__ __launch_bounds__(256)
void proj_gemm(const float* __restrict__ X,
               const float* __restrict__ Wq, const float* __restrict__ Wk,
               const float* __restrict__ Wv, const float* __restrict__ Wb,
               const float* __restrict__ Wg, const float* __restrict__ Wp1,
               const float* __restrict__ Wp2, const float* __restrict__ Wp3)
{
    __shared__ float Xs[2][PBK][PBM];
    __shared__ float Ws[2][PBK][PBN];

    const int tid = threadIdx.x;
    const int m0 = blockIdx.y * PBM;
    const int n0 = blockIdx.x * PBN;

    // load roles: 128 rows x 8 k per tile = 1024 floats = 256 threads * float4
    const int lr = tid >> 1;          // 0..127 : row within tile
    const int lk = (tid & 1) * 4;     // 0 or 4 : k offset

    // compute roles: 16x16 thread grid, 8x8 microtile
    const int tx = tid & 15;
    const int ty = tid >> 4;

    // Resolve weight row pointer for global column (n0 + lr)
    const int n = n0 + lr;
    const float* wrow = nullptr;
    if (n < 2560) {
        const int wi = n >> 9;
        const int nl = n & 511;
        const float* wb = (wi == 0) ? Wq : (wi == 1) ? Wk : (wi == 2) ? Wv
                         : (wi == 3) ? Wb : Wg;
        wrow = wb + nl * DIM_;
    } else if (n < NPROJ) {
        const int nn = n - 2560;
        const int wi = nn >> 5;
        const int nl = nn & 31;
        const float* wb = (wi == 0) ? Wp1 : (wi == 1) ? Wp2 : Wp3;
        wrow = wb + nl * DIM_;
    }
    const float* xrow = X + (size_t)(m0 + lr) * DIM_;

    float acc[8][8];
#pragma unroll
    for (int i = 0; i < 8; i++)
#pragma unroll
        for (int j = 0; j < 8; j++) acc[i][j] = 0.f;

    // prologue: stage tile 0
    {
        float4 xv = *(const float4*)(xrow + lk);
        float4 wv = make_float4(0.f,0.f,0.f,0.f);
        if (wrow) wv = *(const float4*)(wrow + lk);
        Xs[0][lk+0][lr] = xv.x; Xs[0][lk+1][lr] = xv.y;
        Xs[0][lk+2][lr] = xv.z; Xs[0][lk+3][lr] = xv.w;
        Ws[0][lk+0][lr] = wv.x; Ws[0][lk+1][lr] = wv.y;
        Ws[0][lk+2][lr] = wv.z; Ws[0][lk+3][lr] = wv.w;
    }
    __syncthreads();

    const int NKT = DIM_ / PBK;   // 64
    for (int kt = 0; kt < NKT; kt++) {
        const int buf = kt & 1;
        float4 nxv, nwv;
        if (kt < NKT - 1) {
            const int koff = (kt + 1) * PBK + lk;
            nxv = *(const float4*)(xrow + koff);
            nwv = make_float4(0.f,0.f,0.f,0.f);
            if (wrow) nwv = *(const float4*)(wrow + koff);
        }
#pragma unroll
        for (int kk = 0; kk < PBK; kk++) {
            float4 a0 = *(const float4*)&Xs[buf][kk][ty * 8];
            float4 a1 = *(const float4*)&Xs[buf][kk][ty * 8 + 4];
            float4 b0 = *(const float4*)&Ws[buf][kk][tx * 8];
            float4 b1 = *(const float4*)&Ws[buf][kk][tx * 8 + 4];
            float av[8] = {a0.x,a0.y,a0.z,a0.w,a1.x,a1.y,a1.z,a1.w};
            float bv[8] = {b0.x,b0.y,b0.z,b0.w,b1.x,b1.y,b1.z,b1.w};
#pragma unroll
            for (int i = 0; i < 8; i++)
#pragma unroll
                for (int j = 0; j < 8; j++)
                    acc[i][j] = fmaf(av[i], bv[j], acc[i][j]);
        }
        if (kt < NKT - 1) {
            const int nb = buf ^ 1;
            Xs[nb][lk+0][lr] = nxv.x; Xs[nb][lk+1][lr] = nxv.y;
            Xs[nb][lk+2][lr] = nxv.z; Xs[nb][lk+3][lr] = nxv.w;
            Ws[nb][lk+0][lr] = nwv.x; Ws[nb][lk+1][lr] = nwv.y;
            Ws[nb][lk+2][lr] = nwv.z; Ws[nb][lk+3][lr] = nwv.w;
            __syncthreads();
        }
    }

#pragma unroll
    for (int i = 0; i < 8; i++) {
        const int m = m0 + ty * 8 + i;
        float* dst = g_proj + (size_t)m * NPROJ_PAD + n0 + tx * 8;
        *(float4*)(dst)     = make_float4(acc[i][0], acc[i][1], acc[i][2], acc[i][3]);
        *(float4*)(dst + 4) = make_float4(acc[i][4], acc[i][5], acc[i][6], acc[i][7]);
    }
}

// ---------------------------------------------------------------------------
// GEMM 2 (split-K): partial[ks][m,n] = sum_{k in ks-chunk} attn[m,k]*Wo[n,k]
// BM=64, BN=64, BK=16, 256 threads, 4x4 microtile, K chunk = 128.
// ---------------------------------------------------------------------------
#define OBM 64
#define OBN 64
#define OBK 16

__global__ __launch_bounds__(256)
void out_gemm_sk(const float* __restrict__ Wo)
{
    __shared__ float Xs[OBK][OBM + 4];
    __shared__ float Ws[OBK][OBN + 4];

    const int tid = threadIdx.x;
    const int m0 = blockIdx.y * OBM;
    const int n0 = blockIdx.x * OBN;
    const int ks = blockIdx.z;            // 0..3
    const int kbase = ks * 128;

    const int lr = tid >> 2;
    const int lc = (tid & 3) * 4;
    const int tx = tid & 15;
    const int ty = tid >> 4;

    const float* xrow = g_attn + (size_t)(m0 + lr) * DIM_ + kbase;
    const float* wrow = Wo + (size_t)(n0 + lr) * DIM_ + kbase;

    float acc[4][4];
#pragma unroll
    for (int i = 0; i < 4; i++)
#pragma unroll
        for (int j = 0; j < 4; j++) acc[i][j] = 0.f;

    for (int k0 = 0; k0 < 128; k0 += OBK) {
        float4 xv = *(const float4*)(xrow + k0 + lc);
        float4 wv = *(const float4*)(wrow + k0 + lc);
        Xs[lc + 0][lr] = xv.x; Xs[lc + 1][lr] = xv.y;
        Xs[lc + 2][lr] = xv.z; Xs[lc + 3][lr] = xv.w;
        Ws[lc + 0][lr] = wv.x; Ws[lc + 1][lr] = wv.y;
        Ws[lc + 2][lr] = wv.z; Ws[lc + 3][lr] = wv.w;
        __syncthreads();
#pragma unroll
        for (int kk = 0; kk < OBK; kk++) {
            float4 a = *(const float4*)&Xs[kk][ty * 4];
            float4 bq = *(const float4*)&Ws[kk][tx * 4];
            float av[4] = {a.x, a.y, a.z, a.w};
            float bv[4] = {bq.x, bq.y, bq.z, bq.w};
#pragma unroll
            for (int i = 0; i < 4; i++)
#pragma unroll
                for (int j = 0; j < 4; j++)
                    acc[i][j] = fmaf(av[i], bv[j], acc[i][j]);
        }
        __syncthreads();
    }

    float* base = g_outp + (size_t)ks * MROWS * DIM_;
#pragma unroll
    for (int i = 0; i < 4; i++) {
        const int m = m0 + ty * 4 + i;
#pragma unroll
        for (int j = 0; j < 4; j++)
            base[(size_t)m * DIM_ + n0 + tx * 4 + j] = acc[i][j];
    }
}

// Reduce split-K partials + bias -> d_out (vectorized float4)
__global__ __launch_bounds__(256)
void out_reduce(const float* __restrict__ bo, float* __restrict__ out)
{
    const int idx = blockIdx.x * blockDim.x + threadIdx.x;  // float4 index
    const int base = idx * 4;
    if (base >= MROWS * DIM_) return;
    const int n = base & (DIM_ - 1);
    float4 s  = *(const float4*)(g_outp + base);
    float4 s1 = *(const float4*)(g_outp + MROWS*DIM_ + base);
    float4 s2 = *(const float4*)(g_outp + 2*MROWS*DIM_ + base);
    float4 s3 = *(const float4*)(g_outp + 3*MROWS*DIM_ + base);
    float4 bb = *(const float4*)(bo + n);
    float4 r;
    r.x = s.x + s1.x + s2.x + s3.x + bb.x;
    r.y = s.y + s1.y + s2.y + s3.y + bb.y;
    r.z = s.z + s1.z + s2.z + s3.z + bb.z;
    r.w = s.w + s1.w + s2.w + s3.w + bb.w;
    *(float4*)(out + base) = r;
}

// ---------------------------------------------------------------------------
// Scan kernel: one block per (b, h).  256 threads.  (unchanged from R2)
// ---------------------------------------------------------------------------
__device__ __forceinline__ float sigmoidf_(float x) {
    return 1.f / (1.f + __expf(-x));
}

__global__ __launch_bounds__(256)
void scan_kernel(const int* __restrict__ term,
                 const float* __restrict__ kv_prev,
                 const float* __restrict__ nm_prev,
                 float* __restrict__ kv_out,
                 float* __restrict__ nm_out)
{
    const int bh = blockIdx.x;       // 0..127
    const int b  = bh >> 3;
    const int h  = bh & 7;
    const int tid = threadIdx.x;
    const int eg = tid >> 6;         // 0..3
    const int d  = tid & 63;
    const int ED = tid;
    const int e  = ED >> 6;
    const int dd = ED & 63;

    __shared__ float s_disc[FD_];
    __shared__ float s_gk[FD_];
    __shared__ float s_phi[FD_];
    __shared__ float s_gv[DH_];
    __shared__ float s_numred[4][DH_];
    __shared__ float s_denred[8];
    __shared__ float s_den;

    float kv[64];
    const float* kvp = kv_prev + (size_t)bh * FD_ * DH_;
#pragma unroll
    for (int j = 0; j < 64; j++) kv[j] = kvp[(eg * 64 + j) * DH_ + d];
    float nm = nm_prev[bh * FD_ + ED];

    const int hcol = h * DH_;

    for (int t = 0; t < T_; t++) {
        const int row = t * B_ + b;
        const float* P = g_proj + (size_t)row * NPROJ_PAD;

        // ---- phase A: per-ED quantities ----
        const float kdd    = P[512 + hcol + dd];
        const float sgamma = sigmoidf_(P[2048 + hcol + dd]);
        const float p1e = P[2560 + h * ETA_ + e];
        const float p2e = P[2592 + h * ETA_ + e];
        const float p3e = P[2624 + h * ETA_ + e];
        const float gf  = sigmoidf_(p3e) * sgamma;
        const float mask = term[t * B_ + b] ? 0.f : 1.f;
        const float disc = (1.f - gf) * mask;
        const float gkv  = fmaxf(p1e, 0.f) * kdd * gf;
        const float qdd  = P[hcol + dd];
        const float phi  = fmaxf(p2e, 0.f) * qdd;

        s_disc[ED] = disc;
        s_gk[ED]   = gkv;
        s_phi[ED]  = phi;

        nm = disc * nm + gkv;
        float denp = phi * nm;
#pragma unroll
        for (int o = 16; o; o >>= 1)
            denp += __shfl_xor_sync(0xFFFFFFFFu, denp, o);
        if ((tid & 31) == 0) s_denred[tid >> 5] = denp;

        if (tid < 64) {
            const float vv = P[1024 + hcol + tid];
            const float bb = P[1536 + hcol + tid];
            s_gv[tid] = vv * sigmoidf_(bb);
        }
        __syncthreads();

        if (tid == 0) {
            float den = 0.f;
#pragma unroll
            for (int w = 0; w < 8; w++) den += s_denred[w];
            s_den = den;
        }

        // ---- phase B: kv recurrence + num contraction ----
        const float gvd = s_gv[d];
        const float* dsc = &s_disc[eg * 64];
        const float* gks = &s_gk[eg * 64];
        const float* phs = &s_phi[eg * 64];
        float np = 0.f;
#pragma unroll
        for (int jq = 0; jq < 16; jq++) {
            float4 D  = ((const float4*)dsc)[jq];
            float4 G  = ((const float4*)gks)[jq];
            float4 Ph = ((const float4*)phs)[jq];
            float k0v = fmaf(D.x, kv[4*jq+0], gvd * G.x);
            float k1v = fmaf(D.y, kv[4*jq+1], gvd * G.y);
            float k2v = fmaf(D.z, kv[4*jq+2], gvd * G.z);
            float k3v = fmaf(D.w, kv[4*jq+3], gvd * G.w);
            kv[4*jq+0] = k0v; kv[4*jq+1] = k1v;
            kv[4*jq+2] = k2v; kv[4*jq+3] = k3v;
            np = fmaf(k0v, Ph.x, np);
            np = fmaf(k1v, Ph.y, np);
            np = fmaf(k2v, Ph.z, np);
            np = fmaf(k3v, Ph.w, np);
        }
        s_numred[eg][d] = np;
        __syncthreads();

        // ---- phase C: finalize attn_out ----
        if (tid < 64) {
            const float num = s_numred[0][tid] + s_numred[1][tid]
                            + s_numred[2][tid] + s_numred[3][tid];
            g_attn[(size_t)row * (H_*DH_) + hcol + tid] = num / (s_den + 1e-6f);
        }
    }

    float* kvo = kv_out + (size_t)bh * FD_ * DH_;
#pragma unroll
    for (int j = 0; j < 64; j++) kvo[(eg * 64 + j) * DH_ + d] = kv[j];
    nm_out[bh * FD_ + ED] = nm;
}

// ---------------------------------------------------------------------------
// Launch
// ---------------------------------------------------------------------------
extern "C" void kernel_launch(void* const* d_in, const int* in_sizes, int n_in,
                              void* d_out, int out_size)
{
    const float* X    = (const float*)d_in[0];
    const int*   term = (const int*)d_in[1];
    const float* kvp  = (const float*)d_in[2];
    const float* nmp  = (const float*)d_in[3];
    const float* Wq   = (const float*)d_in[4];
    const float* Wk   = (const float*)d_in[5];
    const float* Wv   = (const float*)d_in[6];
    const float* Wb   = (const float*)d_in[7];
    const float* Wg   = (const float*)d_in[8];
    const float* Wp1  = (const float*)d_in[9];
    const float* Wp2  = (const float*)d_in[10];
    const float* Wp3  = (const float*)d_in[11];
    const float* Wo   = (const float*)d_in[12];
    const float* bo   = (const float*)d_in[13];
    float* out = (float*)d_out;

    dim3 gp(NPROJ_PAD / PBN, MROWS / PBM);     // 21 x 8 = 168 blocks
    proj_gemm<<<gp, 256>>>(X, Wq, Wk, Wv, Wb, Wg, Wp1, Wp2, Wp3);

    scan_kernel<<<B_ * H_, 256>>>(term, kvp, nmp,
                                  out + OUT_OFF_KV, out + OUT_OFF_NM);

    dim3 go(DIM_ / OBN, MROWS / OBM, 4);       // 8 x 16 x 4 = 512 blocks
    out_gemm_sk<<<go, 256>>>(Wo);

    out_reduce<<<(MROWS * DIM_ / 4 + 255) / 256, 256>>>(bo, out);
}

// round 5
// speedup vs baseline: 1.4909x; 1.4909x over previous
#include <cuda_runtime.h>
#include <cuda_bf16.h>
#include <cstdint>

// Problem constants
#define T_ 64
#define B_ 16
#define DIM_ 512
#define H_ 8
#define DH_ 64
#define ETA_ 4
#define FD_ 256           // ETA_*DH_
#define NPROJ 2656        // 5*512 + 3*32
#define NPROJ_PAD 2688
#define MROWS 1024        // T_*B_

// Output layout (tuple flattened): output[T,B,DIM], kv_last[B,H,FD,Dh], nm_last[B,H,FD]
#define OUT_OFF_KV  (T_*B_*DIM_)                 // 524288
#define OUT_OFF_NM  (OUT_OFF_KV + B_*H_*FD_*DH_) // 524288 + 2097152

// Scratch (device globals — no allocation allowed)
__device__ float g_proj[MROWS * NPROJ_PAD];        // ~11 MB, projections row-major
__device__ float g_attn[MROWS * (H_*DH_)];         // 2 MB, attn_out before Wo
__device__ float g_outp[4 * MROWS * DIM_];         // 8 MB, split-K partials

// ---------------------------------------------------------------------------
// f32x2 packed helpers (FFMA2 — only reachable via PTX)
// ---------------------------------------------------------------------------
__device__ __forceinline__ unsigned long long pk2(float lo, float hi) {
    unsigned long long r;
    asm("mov.b64 %0, {%1, %2};" : "=l"(r) : "f"(lo), "f"(hi));
    return r;
}
__device__ __forceinline__ void unpk2(float& lo, float& hi, unsigned long long v) {
    asm("mov.b64 {%0, %1}, %2;" : "=f"(lo), "=f"(hi) : "l"(v));
}
__device__ __forceinline__ unsigned long long fma2_(unsigned long long a,
                                                    unsigned long long b,
                                                    unsigned long long c) {
    unsigned long long d;
    asm("fma.rn.f32x2 %0, %1, %2, %3;" : "=l"(d) : "l"(a), "l"(b), "l"(c));
    return d;
}
__device__ __forceinline__ unsigned long long mul2_(unsigned long long a,
                                                    unsigned long long b) {
    unsigned long long d;
    asm("mul.rn.f32x2 %0, %1, %2;" : "=l"(d) : "l"(a), "l"(b));
    return d;
}

// ---------------------------------------------------------------------------
// GEMM 1: projections (R3 measured config: 64x64x16, 4x4 micro, 256 thr)
// ---------------------------------------------------------------------------
#define BM 64
#define BN 64
#define BK 16

__global__ __launch_bounds__(256)
void proj_gemm(const float* __restrict__ X,
               const float* __restrict__ Wq, const float* __restrict__ Wk,
               const float* __restrict__ Wv, const float* __restrict__ Wb,
               const float* __restrict__ Wg, const float* __restrict__ Wp1,
               const float* __restrict__ Wp2, const float* __restrict__ Wp3)
{
    __shared__ float Xs[BK][BM + 4];
    __shared__ float Ws[BK][BN + 4];

    const int tid = threadIdx.x;
    const int m0 = blockIdx.y * BM;
    const int n0 = blockIdx.x * BN;

    const int lr = tid >> 2;          // 0..63 : row within tile
    const int lc = (tid & 3) * 4;     // 0,4,8,12 : k offset
    const int tx = tid & 15;          // n micro
    const int ty = tid >> 4;          // m micro

    const int n = n0 + lr;
    const float* wrow = nullptr;
    if (n < 2560) {
        const int wi = n >> 9;
        const int nl = n & 511;
        const float* wb = (wi == 0) ? Wq : (wi == 1) ? Wk : (wi == 2) ? Wv
                         : (wi == 3) ? Wb : Wg;
        wrow = wb + nl * DIM_;
    } else if (n < NPROJ) {
        const int nn = n - 2560;
        const int wi = nn >> 5;
        const int nl = nn & 31;
        const float* wb = (wi == 0) ? Wp1 : (wi == 1) ? Wp2 : Wp3;
        wrow = wb + nl * DIM_;
    }
    const float* xrow = X + (size_t)(m0 + lr) * DIM_;

    float acc[4][4];
#pragma unroll
    for (int i = 0; i < 4; i++)
#pragma unroll
        for (int j = 0; j < 4; j++) acc[i][j] = 0.f;

    for (int k0 = 0; k0 < DIM_; k0 += BK) {
        float4 xv = *(const float4*)(xrow + k0 + lc);
        float4 wv = make_float4(0.f, 0.f, 0.f, 0.f);
        if (wrow) wv = *(const float4*)(wrow + k0 + lc);
        Xs[lc + 0][lr] = xv.x; Xs[lc + 1][lr] = xv.y;
        Xs[lc + 2][lr] = xv.z; Xs[lc + 3][lr] = xv.w;
        Ws[lc + 0][lr] = wv.x; Ws[lc + 1][lr] = wv.y;
        Ws[lc + 2][lr] = wv.z; Ws[lc + 3][lr] = wv.w;
        __syncthreads();
#pragma unroll
        for (int kk = 0; kk < BK; kk++) {
            float4 a = *(const float4*)&Xs[kk][ty * 4];
            float4 bq = *(const float4*)&Ws[kk][tx * 4];
            float av[4] = {a.x, a.y, a.z, a.w};
            float bv[4] = {bq.x, bq.y, bq.z, bq.w};
#pragma unroll
            for (int i = 0; i < 4; i++)
#pragma unroll
                for (int j = 0; j < 4; j++) acc[i][j] += av[i] * bv[j];
        }
        __syncthreads();
    }

#pragma unroll
    for (int i = 0; i < 4; i++) {
        const int m = m0 + ty * 4 + i;
#pragma unroll
        for (int j = 0; j < 4; j++) {
            g_proj[(size_t)m * NPROJ_PAD + n0 + tx * 4 + j] = acc[i][j];
        }
    }
}

// ---------------------------------------------------------------------------
// GEMM 2 (split-K): partial[ks][m,n] = sum_{k chunk} attn[m,k]*Wo[n,k]
// ---------------------------------------------------------------------------
__global__ __launch_bounds__(256)
void out_gemm_sk(const float* __restrict__ Wo)
{
    __shared__ float Xs[BK][BM + 4];
    __shared__ float Ws[BK][BN + 4];

    const int tid = threadIdx.x;
    const int m0 = blockIdx.y * BM;
    const int n0 = blockIdx.x * BN;
    const int ks = blockIdx.z;            // 0..3
    const int kbase = ks * 128;

    const int lr = tid >> 2;
    const int lc = (tid & 3) * 4;
    const int tx = tid & 15;
    const int ty = tid >> 4;

    const float* xrow = g_attn + (size_t)(m0 + lr) * DIM_ + kbase;
    const float* wrow = Wo + (size_t)(n0 + lr) * DIM_ + kbase;

    float acc[4][4];
#pragma unroll
    for (int i = 0; i < 4; i++)
#pragma unroll
        for (int j = 0; j < 4; j++) acc[i][j] = 0.f;

    for (int k0 = 0; k0 < 128; k0 += BK) {
        float4 xv = *(const float4*)(xrow + k0 + lc);
        float4 wv = *(const float4*)(wrow + k0 + lc);
        Xs[lc + 0][lr] = xv.x; Xs[lc + 1][lr] = xv.y;
        Xs[lc + 2][lr] = xv.z; Xs[lc + 3][lr] = xv.w;
        Ws[lc + 0][lr] = wv.x; Ws[lc + 1][lr] = wv.y;
        Ws[lc + 2][lr] = wv.z; Ws[lc + 3][lr] = wv.w;
        __syncthreads();
#pragma unroll
        for (int kk = 0; kk < BK; kk++) {
            float4 a = *(const float4*)&Xs[kk][ty * 4];
            float4 bq = *(const float4*)&Ws[kk][tx * 4];
            float av[4] = {a.x, a.y, a.z, a.w};
            float bv[4] = {bq.x, bq.y, bq.z, bq.w};
#pragma unroll
            for (int i = 0; i < 4; i++)
#pragma unroll
                for (int j = 0; j < 4; j++)
                    acc[i][j] = fmaf(av[i], bv[j], acc[i][j]);
        }
        __syncthreads();
    }

    float* base = g_outp + (size_t)ks * MROWS * DIM_;
#pragma unroll
    for (int i = 0; i < 4; i++) {
        const int m = m0 + ty * 4 + i;
#pragma unroll
        for (int j = 0; j < 4; j++)
            base[(size_t)m * DIM_ + n0 + tx * 4 + j] = acc[i][j];
    }
}

// Reduce split-K partials + bias -> d_out
__global__ __launch_bounds__(256)
void out_reduce(const float* __restrict__ bo, float* __restrict__ out)
{
    const int idx = blockIdx.x * blockDim.x + threadIdx.x;
    const int base = idx * 4;
    if (base >= MROWS * DIM_) return;
    const int n = base & (DIM_ - 1);
    float4 s  = *(const float4*)(g_outp + base);
    float4 s1 = *(const float4*)(g_outp + MROWS*DIM_ + base);
    float4 s2 = *(const float4*)(g_outp + 2*MROWS*DIM_ + base);
    float4 s3 = *(const float4*)(g_outp + 3*MROWS*DIM_ + base);
    float4 bb = *(const float4*)(bo + n);
    float4 r;
    r.x = s.x + s1.x + s2.x + s3.x + bb.x;
    r.y = s.y + s1.y + s2.y + s3.y + bb.y;
    r.z = s.z + s1.z + s2.z + s3.z + bb.z;
    r.w = s.w + s1.w + s2.w + s3.w + bb.w;
    *(float4*)(out + base) = r;
}

// ---------------------------------------------------------------------------
// Scan kernel (rewritten): one block per (b,h), 256 threads.
//  - global loads for step t+1 prefetched during step t (hides L2 latency)
//  - kv state + recurrence in packed f32x2 (fma.rn.f32x2) — halves FMA instrs
// ---------------------------------------------------------------------------
__device__ __forceinline__ float sigmoidf_(float x) {
    return 1.f / (1.f + __expf(-x));
}

__global__ __launch_bounds__(256)
void scan_kernel(const int* __restrict__ term,
                 const float* __restrict__ kv_prev,
                 const float* __restrict__ nm_prev,
                 float* __restrict__ kv_out,
                 float* __restrict__ nm_out)
{
    const int bh = blockIdx.x;       // 0..127
    const int b  = bh >> 3;
    const int h  = bh & 7;
    const int tid = threadIdx.x;
    const int eg = tid >> 6;         // 0..3
    const int d  = tid & 63;
    const int ED = tid;
    const int e  = ED >> 6;
    const int dd = ED & 63;

    __shared__ float s_disc[FD_];
    __shared__ float s_gk[FD_];
    __shared__ float s_phi[FD_];
    __shared__ float s_gv[DH_];
    __shared__ float s_numred[4][DH_];
    __shared__ float s_denred[8];
    __shared__ float s_den;

    // kv state as 32 packed f32x2 (pairs of adjacent feature rows j, j+1)
    unsigned long long kv2[32];
    {
        const float* kvp = kv_prev + (size_t)bh * FD_ * DH_;
#pragma unroll
        for (int p = 0; p < 32; p++) {
            const float lo = kvp[(eg * 64 + 2*p    ) * DH_ + d];
            const float hi = kvp[(eg * 64 + 2*p + 1) * DH_ + d];
            kv2[p] = pk2(lo, hi);
        }
    }
    float nm = nm_prev[bh * FD_ + ED];

    const int hcol = h * DH_;
    const int pofs = h * ETA_ + e;

    // ---- prefetch for t = 0 ----
    float r_q, r_k, r_g, r_p1, r_p2, r_p3, r_v, r_b;
    int r_term;
    {
        const float* P = g_proj + (size_t)(0 * B_ + b) * NPROJ_PAD;
        r_q  = P[hcol + dd];
        r_k  = P[512 + hcol + dd];
        r_g  = P[2048 + hcol + dd];
        r_p1 = P[2560 + pofs];
        r_p2 = P[2592 + pofs];
        r_p3 = P[2624 + pofs];
        r_term = term[b];
        if (tid < 64) {
            r_v = P[1024 + hcol + tid];
            r_b = P[1536 + hcol + tid];
        }
    }

    for (int t = 0; t < T_; t++) {
        const int row = t * B_ + b;

        // ---- phase A: per-ED quantities from prefetched registers ----
        const float sgamma = sigmoidf_(r_g);
        const float gf   = sigmoidf_(r_p3) * sgamma;
        const float mask = r_term ? 0.f : 1.f;
        const float disc = (1.f - gf) * mask;
        const float gkv  = fmaxf(r_p1, 0.f) * r_k * gf;
        const float phi  = fmaxf(r_p2, 0.f) * r_q;

        s_disc[ED] = disc;
        s_gk[ED]   = gkv;
        s_phi[ED]  = phi;

        if (tid < 64) {
            s_gv[tid] = r_v * sigmoidf_(r_b);
        }

        // ---- prefetch for t+1 (overlaps reduction + barriers + phase B) ----
        if (t + 1 < T_) {
            const float* Pn = g_proj + (size_t)((t + 1) * B_ + b) * NPROJ_PAD;
            r_q  = Pn[hcol + dd];
            r_k  = Pn[512 + hcol + dd];
            r_g  = Pn[2048 + hcol + dd];
            r_p1 = Pn[2560 + pofs];
            r_p2 = Pn[2592 + pofs];
            r_p3 = Pn[2624 + pofs];
            r_term = term[(t + 1) * B_ + b];
            if (tid < 64) {
                r_v = Pn[1024 + hcol + tid];
                r_b = Pn[1536 + hcol + tid];
            }
        }

        nm = fmaf(disc, nm, gkv);
        float denp = phi * nm;
#pragma unroll
        for (int o = 16; o; o >>= 1)
            denp += __shfl_xor_sync(0xFFFFFFFFu, denp, o);
        if ((tid & 31) == 0) s_denred[tid >> 5] = denp;

        __syncthreads();

        if (tid == 0) {
            float den = 0.f;
#pragma unroll
            for (int w = 0; w < 8; w++) den += s_denred[w];
            s_den = den;
        }

        // ---- phase B: packed kv recurrence + num contraction ----
        const unsigned long long gvd2 = pk2(s_gv[d], s_gv[d]);
        const ulonglong2* dsc2 = (const ulonglong2*)&s_disc[eg * 64];
        const ulonglong2* gks2 = (const ulonglong2*)&s_gk[eg * 64];
        const ulonglong2* phs2 = (const ulonglong2*)&s_phi[eg * 64];
        unsigned long long np01 = 0ULL, np23 = 0ULL;
#pragma unroll
        for (int jq = 0; jq < 16; jq++) {
            const ulonglong2 D = dsc2[jq];
            const ulonglong2 G = gks2[jq];
            const ulonglong2 Ph = phs2[jq];
            kv2[2*jq]     = fma2_(D.x, kv2[2*jq],     mul2_(gvd2, G.x));
            kv2[2*jq + 1] = fma2_(D.y, kv2[2*jq + 1], mul2_(gvd2, G.y));
            np01 = fma2_(kv2[2*jq],     Ph.x, np01);
            np23 = fma2_(kv2[2*jq + 1], Ph.y, np23);
        }
        {
            float a0, a1, a2, a3;
            unpk2(a0, a1, np01);
            unpk2(a2, a3, np23);
            s_numred[eg][d] = (a0 + a1) + (a2 + a3);
        }
        __syncthreads();

        // ---- phase C: finalize attn_out ----
        if (tid < 64) {
            const float num = s_numred[0][tid] + s_numred[1][tid]
                            + s_numred[2][tid] + s_numred[3][tid];
            g_attn[(size_t)row * (H_*DH_) + hcol + tid] = num / (s_den + 1e-6f);
        }
        // next phase-A writes disjoint shared arrays; s_den/s_numred reads of
        // this step complete before the next __syncthreads they depend on.
    }

    // Write final states
    float* kvo = kv_out + (size_t)bh * FD_ * DH_;
#pragma unroll
    for (int p = 0; p < 32; p++) {
        float lo, hi;
        unpk2(lo, hi, kv2[p]);
        kvo[(eg * 64 + 2*p    ) * DH_ + d] = lo;
        kvo[(eg * 64 + 2*p + 1) * DH_ + d] = hi;
    }
    nm_out[bh * FD_ + ED] = nm;
}

// ---------------------------------------------------------------------------
// Launch
// ---------------------------------------------------------------------------
extern "C" void kernel_launch(void* const* d_in, const int* in_sizes, int n_in,
                              void* d_out, int out_size)
{
    const float* X    = (const float*)d_in[0];
    const int*   term = (const int*)d_in[1];
    const float* kvp  = (const float*)d_in[2];
    const float* nmp  = (const float*)d_in[3];
    const float* Wq   = (const float*)d_in[4];
    const float* Wk   = (const float*)d_in[5];
    const float* Wv   = (const float*)d_in[6];
    const float* Wb   = (const float*)d_in[7];
    const float* Wg   = (const float*)d_in[8];
    const float* Wp1  = (const float*)d_in[9];
    const float* Wp2  = (const float*)d_in[10];
    const float* Wp3  = (const float*)d_in[11];
    const float* Wo   = (const float*)d_in[12];
    const float* bo   = (const float*)d_in[13];
    float* out = (float*)d_out;

    dim3 gp(NPROJ_PAD / BN, MROWS / BM);       // 42 x 16 = 672 blocks
    proj_gemm<<<gp, 256>>>(X, Wq, Wk, Wv, Wb, Wg, Wp1, Wp2, Wp3);

    scan_kernel<<<B_ * H_, 256>>>(term, kvp, nmp,
                                  out + OUT_OFF_KV, out + OUT_OFF_NM);

    dim3 go(DIM_ / BN, MROWS / BM, 4);         // 8 x 16 x 4 = 512 blocks
    out_gemm_sk<<<go, 256>>>(Wo);

    out_reduce<<<(MROWS * DIM_ / 4 + 255) / 256, 256>>>(bo, out);
}

// round 6
// speedup vs baseline: 1.5302x; 1.0263x over previous
#include <cuda_runtime.h>
#include <cuda_bf16.h>
#include <cstdint>

// Problem constants
#define T_ 64
#define B_ 16
#define DIM_ 512
#define H_ 8
#define DH_ 64
#define ETA_ 4
#define FD_ 256           // ETA_*DH_
#define NPROJ 2656        // 5*512 + 3*32
#define NPROJ_PAD 2688
#define MROWS 1024        // T_*B_

// Output layout (tuple flattened): output[T,B,DIM], kv_last[B,H,FD,Dh], nm_last[B,H,FD]
#define OUT_OFF_KV  (T_*B_*DIM_)                 // 524288
#define OUT_OFF_NM  (OUT_OFF_KV + B_*H_*FD_*DH_) // 524288 + 2097152

// Scratch (device globals — no allocation allowed)
__device__ float g_proj[MROWS * NPROJ_PAD];        // ~11 MB, projections row-major
__device__ float g_attn[MROWS * (H_*DH_)];         // 2 MB, attn_out before Wo
__device__ float g_outp[2 * MROWS * DIM_];         // 4 MB, split-K partials

// ---------------------------------------------------------------------------
// f32x2 packed helpers (FFMA2 — only reachable via PTX)
// ---------------------------------------------------------------------------
__device__ __forceinline__ unsigned long long pk2(float lo, float hi) {
    unsigned long long r;
    asm("mov.b64 %0, {%1, %2};" : "=l"(r) : "f"(lo), "f"(hi));
    return r;
}
__device__ __forceinline__ void unpk2(float& lo, float& hi, unsigned long long v) {
    asm("mov.b64 {%0, %1}, %2;" : "=f"(lo), "=f"(hi) : "l"(v));
}
__device__ __forceinline__ unsigned long long fma2_(unsigned long long a,
                                                    unsigned long long b,
                                                    unsigned long long c) {
    unsigned long long d;
    asm("fma.rn.f32x2 %0, %1, %2, %3;" : "=l"(d) : "l"(a), "l"(b), "l"(c));
    return d;
}
__device__ __forceinline__ unsigned long long mul2_(unsigned long long a,
                                                    unsigned long long b) {
    unsigned long long d;
    asm("mul.rn.f32x2 %0, %1, %2;" : "=l"(d) : "l"(a), "l"(b));
    return d;
}

// ---------------------------------------------------------------------------
// GEMM 1: projections (R3 measured config: 64x64x16, 4x4 micro, 256 thr)
// ---------------------------------------------------------------------------
#define BM 64
#define BN 64
#define BK 16

__global__ __launch_bounds__(256)
void proj_gemm(const float* __restrict__ X,
               const float* __restrict__ Wq, const float* __restrict__ Wk,
               const float* __restrict__ Wv, const float* __restrict__ Wb,
               const float* __restrict__ Wg, const float* __restrict__ Wp1,
               const float* __restrict__ Wp2, const float* __restrict__ Wp3)
{
    __shared__ float Xs[BK][BM + 4];
    __shared__ float Ws[BK][BN + 4];

    const int tid = threadIdx.x;
    const int m0 = blockIdx.y * BM;
    const int n0 = blockIdx.x * BN;

    const int lr = tid >> 2;          // 0..63 : row within tile
    const int lc = (tid & 3) * 4;     // 0,4,8,12 : k offset
    const int tx = tid & 15;          // n micro
    const int ty = tid >> 4;          // m micro

    const int n = n0 + lr;
    const float* wrow = nullptr;
    if (n < 2560) {
        const int wi = n >> 9;
        const int nl = n & 511;
        const float* wb = (wi == 0) ? Wq : (wi == 1) ? Wk : (wi == 2) ? Wv
                         : (wi == 3) ? Wb : Wg;
        wrow = wb + nl * DIM_;
    } else if (n < NPROJ) {
        const int nn = n - 2560;
        const int wi = nn >> 5;
        const int nl = nn & 31;
        const float* wb = (wi == 0) ? Wp1 : (wi == 1) ? Wp2 : Wp3;
        wrow = wb + nl * DIM_;
    }
    const float* xrow = X + (size_t)(m0 + lr) * DIM_;

    float acc[4][4];
#pragma unroll
    for (int i = 0; i < 4; i++)
#pragma unroll
        for (int j = 0; j < 4; j++) acc[i][j] = 0.f;

    for (int k0 = 0; k0 < DIM_; k0 += BK) {
        float4 xv = *(const float4*)(xrow + k0 + lc);
        float4 wv = make_float4(0.f, 0.f, 0.f, 0.f);
        if (wrow) wv = *(const float4*)(wrow + k0 + lc);
        Xs[lc + 0][lr] = xv.x; Xs[lc + 1][lr] = xv.y;
        Xs[lc + 2][lr] = xv.z; Xs[lc + 3][lr] = xv.w;
        Ws[lc + 0][lr] = wv.x; Ws[lc + 1][lr] = wv.y;
        Ws[lc + 2][lr] = wv.z; Ws[lc + 3][lr] = wv.w;
        __syncthreads();
#pragma unroll
        for (int kk = 0; kk < BK; kk++) {
            float4 a = *(const float4*)&Xs[kk][ty * 4];
            float4 bq = *(const float4*)&Ws[kk][tx * 4];
            float av[4] = {a.x, a.y, a.z, a.w};
            float bv[4] = {bq.x, bq.y, bq.z, bq.w};
#pragma unroll
            for (int i = 0; i < 4; i++)
#pragma unroll
                for (int j = 0; j < 4; j++) acc[i][j] += av[i] * bv[j];
        }
        __syncthreads();
    }

#pragma unroll
    for (int i = 0; i < 4; i++) {
        const int m = m0 + ty * 4 + i;
#pragma unroll
        for (int j = 0; j < 4; j++) {
            g_proj[(size_t)m * NPROJ_PAD + n0 + tx * 4 + j] = acc[i][j];
        }
    }
}

// ---------------------------------------------------------------------------
// GEMM 2 (split-K = 2): partial[ks][m,n] = sum_{k chunk 256} attn[m,k]*Wo[n,k]
// ---------------------------------------------------------------------------
__global__ __launch_bounds__(256)
void out_gemm_sk(const float* __restrict__ Wo)
{
    __shared__ float Xs[BK][BM + 4];
    __shared__ float Ws[BK][BN + 4];

    const int tid = threadIdx.x;
    const int m0 = blockIdx.y * BM;
    const int n0 = blockIdx.x * BN;
    const int ks = blockIdx.z;            // 0..1
    const int kbase = ks * 256;

    const int lr = tid >> 2;
    const int lc = (tid & 3) * 4;
    const int tx = tid & 15;
    const int ty = tid >> 4;

    const float* xrow = g_attn + (size_t)(m0 + lr) * DIM_ + kbase;
    const float* wrow = Wo + (size_t)(n0 + lr) * DIM_ + kbase;

    float acc[4][4];
#pragma unroll
    for (int i = 0; i < 4; i++)
#pragma unroll
        for (int j = 0; j < 4; j++) acc[i][j] = 0.f;

    for (int k0 = 0; k0 < 256; k0 += BK) {
        float4 xv = *(const float4*)(xrow + k0 + lc);
        float4 wv = *(const float4*)(wrow + k0 + lc);
        Xs[lc + 0][lr] = xv.x; Xs[lc + 1][lr] = xv.y;
        Xs[lc + 2][lr] = xv.z; Xs[lc + 3][lr] = xv.w;
        Ws[lc + 0][lr] = wv.x; Ws[lc + 1][lr] = wv.y;
        Ws[lc + 2][lr] = wv.z; Ws[lc + 3][lr] = wv.w;
        __syncthreads();
#pragma unroll
        for (int kk = 0; kk < BK; kk++) {
            float4 a = *(const float4*)&Xs[kk][ty * 4];
            float4 bq = *(const float4*)&Ws[kk][tx * 4];
            float av[4] = {a.x, a.y, a.z, a.w};
            float bv[4] = {bq.x, bq.y, bq.z, bq.w};
#pragma unroll
            for (int i = 0; i < 4; i++)
#pragma unroll
                for (int j = 0; j < 4; j++)
                    acc[i][j] = fmaf(av[i], bv[j], acc[i][j]);
        }
        __syncthreads();
    }

    float* base = g_outp + (size_t)ks * MROWS * DIM_;
#pragma unroll
    for (int i = 0; i < 4; i++) {
        const int m = m0 + ty * 4 + i;
#pragma unroll
        for (int j = 0; j < 4; j++)
            base[(size_t)m * DIM_ + n0 + tx * 4 + j] = acc[i][j];
    }
}

// Reduce split-K partials + bias -> d_out
__global__ __launch_bounds__(256)
void out_reduce(const float* __restrict__ bo, float* __restrict__ out)
{
    const int idx = blockIdx.x * blockDim.x + threadIdx.x;
    const int base = idx * 4;
    if (base >= MROWS * DIM_) return;
    const int n = base & (DIM_ - 1);
    float4 s  = *(const float4*)(g_outp + base);
    float4 s1 = *(const float4*)(g_outp + MROWS*DIM_ + base);
    float4 bb = *(const float4*)(bo + n);
    float4 r;
    r.x = s.x + s1.x + bb.x;
    r.y = s.y + s1.y + bb.y;
    r.z = s.z + s1.z + bb.z;
    r.w = s.w + s1.w + bb.w;
    *(float4*)(out + base) = r;
}

// ---------------------------------------------------------------------------
// Scan kernel v3: TWO blocks per (b,h), split along Dh (d-halves).
//  - blockIdx.x = bh*2 + ds; block handles d in [ds*32, ds*32+32)
//  - 256 threads: warp index fg = FD group of 32 rows, lane dl = d offset
//  - per-thread kv state: 32 floats = 16 packed f32x2
//  - phase A (per-FD scalars, nm, den) duplicated across the two ds-blocks
// ---------------------------------------------------------------------------
__device__ __forceinline__ float sigmoidf_(float x) {
    return 1.f / (1.f + __expf(-x));
}

__global__ __launch_bounds__(256)
void scan_kernel(const int* __restrict__ term,
                 const float* __restrict__ kv_prev,
                 const float* __restrict__ nm_prev,
                 float* __restrict__ kv_out,
                 float* __restrict__ nm_out)
{
    const int blk = blockIdx.x;      // 0..255
    const int bh  = blk >> 1;        // 0..127
    const int ds  = blk & 1;         // d-half
    const int b   = bh >> 3;
    const int h   = bh & 7;
    const int tid = threadIdx.x;
    const int fg  = tid >> 5;        // 0..7 : FD group (32 rows)
    const int dl  = tid & 31;        // lane
    const int d   = ds * 32 + dl;    // global head-dim column
    const int ED  = tid;             // 0..255 : FD index for phase A
    const int e   = ED >> 6;
    const int dd  = ED & 63;

    __shared__ float s_disc[FD_];
    __shared__ float s_gk[FD_];
    __shared__ float s_phi[FD_];
    __shared__ float s_gv[32];
    __shared__ float s_numred[8][32];
    __shared__ float s_denred[8];
    __shared__ float s_den;

    // kv state: FD rows [fg*32, fg*32+32) for column d, packed in pairs
    unsigned long long kv2[16];
    {
        const float* kvp = kv_prev + (size_t)bh * FD_ * DH_;
#pragma unroll
        for (int p = 0; p < 16; p++) {
            const float lo = kvp[(fg * 32 + 2*p    ) * DH_ + d];
            const float hi = kvp[(fg * 32 + 2*p + 1) * DH_ + d];
            kv2[p] = pk2(lo, hi);
        }
    }
    float nm = nm_prev[bh * FD_ + ED];

    const int hcol = h * DH_;
    const int pofs = h * ETA_ + e;

    // ---- prefetch for t = 0 ----
    float r_q, r_k, r_g, r_p1, r_p2, r_p3, r_v, r_b;
    int r_term;
    {
        const float* P = g_proj + (size_t)b * NPROJ_PAD;
        r_q  = P[hcol + dd];
        r_k  = P[512 + hcol + dd];
        r_g  = P[2048 + hcol + dd];
        r_p1 = P[2560 + pofs];
        r_p2 = P[2592 + pofs];
        r_p3 = P[2624 + pofs];
        r_term = term[b];
        if (tid < 32) {
            r_v = P[1024 + hcol + ds * 32 + tid];
            r_b = P[1536 + hcol + ds * 32 + tid];
        }
    }

    for (int t = 0; t < T_; t++) {
        const int row = t * B_ + b;

        // ---- phase A: per-FD quantities ----
        const float sgamma = sigmoidf_(r_g);
        const float gf   = sigmoidf_(r_p3) * sgamma;
        const float mask = r_term ? 0.f : 1.f;
        const float disc = (1.f - gf) * mask;
        const float gkv  = fmaxf(r_p1, 0.f) * r_k * gf;
        const float phi  = fmaxf(r_p2, 0.f) * r_q;

        s_disc[ED] = disc;
        s_gk[ED]   = gkv;
        s_phi[ED]  = phi;

        if (tid < 32) {
            s_gv[tid] = r_v * sigmoidf_(r_b);
        }

        // ---- prefetch for t+1 (overlaps reduction + barriers + phase B) ----
        if (t + 1 < T_) {
            const float* Pn = g_proj + (size_t)((t + 1) * B_ + b) * NPROJ_PAD;
            r_q  = Pn[hcol + dd];
            r_k  = Pn[512 + hcol + dd];
            r_g  = Pn[2048 + hcol + dd];
            r_p1 = Pn[2560 + pofs];
            r_p2 = Pn[2592 + pofs];
            r_p3 = Pn[2624 + pofs];
            r_term = term[(t + 1) * B_ + b];
            if (tid < 32) {
                r_v = Pn[1024 + hcol + ds * 32 + tid];
                r_b = Pn[1536 + hcol + ds * 32 + tid];
            }
        }

        nm = fmaf(disc, nm, gkv);
        float denp = phi * nm;
#pragma unroll
        for (int o = 16; o; o >>= 1)
            denp += __shfl_xor_sync(0xFFFFFFFFu, denp, o);
        if (dl == 0) s_denred[fg] = denp;

        __syncthreads();

        if (tid == 0) {
            float den = 0.f;
#pragma unroll
            for (int w = 0; w < 8; w++) den += s_denred[w];
            s_den = den;
        }

        // ---- phase B: packed kv recurrence + num contraction ----
        // warp-uniform broadcast loads from s_disc/s_gk/s_phi (fg = warp idx)
        const unsigned long long gvd2 = pk2(s_gv[dl], s_gv[dl]);
        const ulonglong2* dsc2 = (const ulonglong2*)&s_disc[fg * 32];
        const ulonglong2* gks2 = (const ulonglong2*)&s_gk[fg * 32];
        const ulonglong2* phs2 = (const ulonglong2*)&s_phi[fg * 32];
        unsigned long long np01 = 0ULL, np23 = 0ULL;
#pragma unroll
        for (int jq = 0; jq < 8; jq++) {
            const ulonglong2 D = dsc2[jq];
            const ulonglong2 G = gks2[jq];
            const ulonglong2 Ph = phs2[jq];
            kv2[2*jq]     = fma2_(D.x, kv2[2*jq],     mul2_(gvd2, G.x));
            kv2[2*jq + 1] = fma2_(D.y, kv2[2*jq + 1], mul2_(gvd2, G.y));
            np01 = fma2_(kv2[2*jq],     Ph.x, np01);
            np23 = fma2_(kv2[2*jq + 1], Ph.y, np23);
        }
        {
            float a0, a1, a2, a3;
            unpk2(a0, a1, np01);
            unpk2(a2, a3, np23);
            s_numred[fg][dl] = (a0 + a1) + (a2 + a3);
        }
        __syncthreads();

        // ---- phase C: finalize attn_out for this d-half ----
        if (tid < 32) {
            float num = 0.f;
#pragma unroll
            for (int g = 0; g < 8; g++) num += s_numred[g][tid];
            g_attn[(size_t)row * (H_*DH_) + hcol + ds * 32 + tid]
                = num / (s_den + 1e-6f);
        }
    }

    // Write final states (kv: this block's d-column slice; nm: ds==0 only)
    float* kvo = kv_out + (size_t)bh * FD_ * DH_;
#pragma unroll
    for (int p = 0; p < 16; p++) {
        float lo, hi;
        unpk2(lo, hi, kv2[p]);
        kvo[(fg * 32 + 2*p    ) * DH_ + d] = lo;
        kvo[(fg * 32 + 2*p + 1) * DH_ + d] = hi;
    }
    if (ds == 0) nm_out[bh * FD_ + ED] = nm;
}

// ---------------------------------------------------------------------------
// Launch
// ---------------------------------------------------------------------------
extern "C" void kernel_launch(void* const* d_in, const int* in_sizes, int n_in,
                              void* d_out, int out_size)
{
    const float* X    = (const float*)d_in[0];
    const int*   term = (const int*)d_in[1];
    const float* kvp  = (const float*)d_in[2];
    const float* nmp  = (const float*)d_in[3];
    const float* Wq   = (const float*)d_in[4];
    const float* Wk   = (const float*)d_in[5];
    const float* Wv   = (const float*)d_in[6];
    const float* Wb   = (const float*)d_in[7];
    const float* Wg   = (const float*)d_in[8];
    const float* Wp1  = (const float*)d_in[9];
    const float* Wp2  = (const float*)d_in[10];
    const float* Wp3  = (const float*)d_in[11];
    const float* Wo   = (const float*)d_in[12];
    const float* bo   = (const float*)d_in[13];
    float* out = (float*)d_out;

    dim3 gp(NPROJ_PAD / BN, MROWS / BM);       // 42 x 16 = 672 blocks
    proj_gemm<<<gp, 256>>>(X, Wq, Wk, Wv, Wb, Wg, Wp1, Wp2, Wp3);

    scan_kernel<<<B_ * H_ * 2, 256>>>(term, kvp, nmp,
                                      out + OUT_OFF_KV, out + OUT_OFF_NM);

    dim3 go(DIM_ / BN, MROWS / BM, 2);         // 8 x 16 x 2 = 256 blocks
    out_gemm_sk<<<go, 256>>>(Wo);

    out_reduce<<<(MROWS * DIM_ / 4 + 255) / 256, 256>>>(bo, out);
}